// round 1
// baseline (speedup 1.0000x reference)
#include <cuda_runtime.h>
#include <math.h>

#define T_LEN 200
#define T_PAD 224          // 7 * 32 rows covered by the register tile
#define E_DIM 64
#define H1 80
#define H2 40
#define NTHREADS 256

#define FSH_STRIDE 65      // 200x64 tile padded -> conflict-free column reads
#define H1_STRIDE 81

// smem sizes (floats)
#define SZ_FSH   (T_PAD * FSH_STRIDE)   // 14560
#define SZ_H1    (T_PAD * H1_STRIDE)    // 18144
#define SZ_WEFF  (E_DIM * H1)           // 5120
#define SZ_W2    (H1 * H2)              // 3200

__device__ __forceinline__ float fast_sigmoid(float x) {
    return __fdividef(1.0f, 1.0f + __expf(-x));
}

__global__ __launch_bounds__(NTHREADS, 1)
void din_atten_kernel(const float* __restrict__ query,
                      const float* __restrict__ facts,
                      const int*   __restrict__ mask,
                      const float* __restrict__ W1,
                      const float* __restrict__ b1,
                      const float* __restrict__ W2,
                      const float* __restrict__ b2,
                      const float* __restrict__ W3,
                      const float* __restrict__ b3,
                      float* __restrict__ out)
{
    extern __shared__ float sm[];
    float* fsh     = sm;                         // [224][65]
    float* h1sh    = fsh   + SZ_FSH;             // [224][81]
    float* weff    = h1sh  + SZ_H1;              // [64][80]
    float* w2sh    = weff  + SZ_WEFF;            // [80][40]
    float* c1sh    = w2sh  + SZ_W2;              // [80]
    float* w3sh    = c1sh  + H1;                 // [40]
    float* b2sh    = w3sh  + H2;                 // [40]
    float* qsh     = b2sh  + H2;                 // [64]
    float* scoresh = qsh   + E_DIM;              // [224]
    float* attnsh  = scoresh + T_PAD;            // [224]
    float* red     = attnsh  + T_PAD;            // [256]
    float* outred  = red     + NTHREADS;         // [256]

    const int b   = blockIdx.x;
    const int tid = threadIdx.x;

    // ---------------- Phase 1: stage inputs ----------------
    if (tid < E_DIM) qsh[tid] = query[(size_t)b * E_DIM + tid];
    for (int i = tid; i < SZ_W2; i += NTHREADS) w2sh[i] = W2[i];
    if (tid < H2) { w3sh[tid] = W3[tid]; b2sh[tid] = b2[tid]; }

    const float* fb = facts + (size_t)b * (T_LEN * E_DIM);
    for (int i = tid; i < T_LEN * E_DIM; i += NTHREADS) {
        int t = i >> 6, e = i & 63;
        fsh[t * FSH_STRIDE + e] = fb[i];
    }
    // zero the padding rows 200..223
    for (int i = tid; i < (T_PAD - T_LEN) * E_DIM; i += NTHREADS) {
        int t = T_LEN + (i >> 6), e = i & 63;
        fsh[t * FSH_STRIDE + e] = 0.0f;
    }
    __syncthreads();

    // ---------------- Phase 2: per-batch effective weights ----------------
    // din@W1 = q@(A+C) + f@(B-C) + (q*f)@D  with W1 = [A;B;C;D] stacked rows.
    for (int i = tid; i < SZ_WEFF; i += NTHREADS) {
        int e = i / H1;
        int h = i - e * H1;
        float wb = W1[(E_DIM     + e) * H1 + h];
        float wc = W1[(2 * E_DIM + e) * H1 + h];
        float wd = W1[(3 * E_DIM + e) * H1 + h];
        weff[i] = wb - wc + qsh[e] * wd;
    }
    if (tid < H1) {
        float acc = b1[tid];
        #pragma unroll 8
        for (int e = 0; e < E_DIM; e++) {
            acc += qsh[e] * (W1[e * H1 + tid] + W1[(2 * E_DIM + e) * H1 + tid]);
        }
        c1sh[tid] = acc;
    }
    {
        float b3v = b3[0];
        for (int t = tid; t < T_PAD; t += NTHREADS) scoresh[t] = b3v;
    }
    __syncthreads();

    const int tr = tid & 31;   // row lane within warp
    const int tc = tid >> 5;   // column group (warp id), 0..7

    // ---------------- Phase 3: GEMM1  h1 = sigmoid(c1 + F @ Weff) ----------------
    {
        float acc[7][10];
        #pragma unroll
        for (int i = 0; i < 7; i++)
            #pragma unroll
            for (int j = 0; j < 10; j++) acc[i][j] = 0.0f;

        #pragma unroll 2
        for (int e = 0; e < E_DIM; e++) {
            float fr[7], wc[10];
            #pragma unroll
            for (int i = 0; i < 7; i++) fr[i] = fsh[(tr + 32 * i) * FSH_STRIDE + e];
            #pragma unroll
            for (int j = 0; j < 10; j++) wc[j] = weff[e * H1 + tc + 8 * j];
            #pragma unroll
            for (int i = 0; i < 7; i++)
                #pragma unroll
                for (int j = 0; j < 10; j++) acc[i][j] += fr[i] * wc[j];
        }
        #pragma unroll
        for (int i = 0; i < 7; i++) {
            int r = tr + 32 * i;
            #pragma unroll
            for (int j = 0; j < 10; j++) {
                int col = tc + 8 * j;
                h1sh[r * H1_STRIDE + col] = fast_sigmoid(acc[i][j] + c1sh[col]);
            }
        }
    }
    __syncthreads();

    // ---------------- Phase 4: GEMM2 + layer3  score += (sigmoid(h1@W2+b2))@W3 ----------------
    {
        float acc[7][5];
        #pragma unroll
        for (int i = 0; i < 7; i++)
            #pragma unroll
            for (int k = 0; k < 5; k++) acc[i][k] = 0.0f;

        #pragma unroll 2
        for (int e = 0; e < H1; e++) {
            float hr[7], wc[5];
            #pragma unroll
            for (int i = 0; i < 7; i++) hr[i] = h1sh[(tr + 32 * i) * H1_STRIDE + e];
            #pragma unroll
            for (int k = 0; k < 5; k++) wc[k] = w2sh[e * H2 + tc + 8 * k];
            #pragma unroll
            for (int i = 0; i < 7; i++)
                #pragma unroll
                for (int k = 0; k < 5; k++) acc[i][k] += hr[i] * wc[k];
        }
        #pragma unroll
        for (int i = 0; i < 7; i++) {
            float s = 0.0f;
            #pragma unroll
            for (int k = 0; k < 5; k++) {
                int col = tc + 8 * k;
                s += fast_sigmoid(acc[i][k] + b2sh[col]) * w3sh[col];
            }
            atomicAdd(&scoresh[tr + 32 * i], s);
        }
    }
    __syncthreads();

    // ---------------- Phase 5: masked softmax over T ----------------
    const float PADV = -4294967295.0f;  // -2^32 + 1
    float v;
    if (tid < T_LEN) {
        v = (mask[(size_t)b * T_LEN + tid] == 1) ? scoresh[tid] : PADV;
    } else {
        v = -INFINITY;
    }
    red[tid] = v;
    __syncthreads();
    #pragma unroll
    for (int off = 128; off > 0; off >>= 1) {
        if (tid < off) red[tid] = fmaxf(red[tid], red[tid + off]);
        __syncthreads();
    }
    float mmax = red[0];
    __syncthreads();
    float p = (tid < T_LEN) ? __expf(v - mmax) : 0.0f;
    red[tid] = p;
    __syncthreads();
    #pragma unroll
    for (int off = 128; off > 0; off >>= 1) {
        if (tid < off) red[tid] += red[tid + off];
        __syncthreads();
    }
    float inv = 1.0f / red[0];
    if (tid < T_LEN) attnsh[tid] = p * inv;
    __syncthreads();

    // ---------------- Phase 6: out[b] = attn @ facts ----------------
    {
        int e = tid & 63;
        int c = tid >> 6;       // 4 chunks of 50 timesteps
        float acc = 0.0f;
        int t0 = c * 50;
        #pragma unroll 5
        for (int t = t0; t < t0 + 50; t++) acc += attnsh[t] * fsh[t * FSH_STRIDE + e];
        outred[c * 64 + e] = acc;
    }
    __syncthreads();
    if (tid < 64) {
        out[(size_t)b * E_DIM + tid] =
            outred[tid] + outred[64 + tid] + outred[128 + tid] + outred[192 + tid];
    }
}

#define SMEM_FLOATS (SZ_FSH + SZ_H1 + SZ_WEFF + SZ_W2 + H1 + H2 + H2 + E_DIM + \
                     T_PAD + T_PAD + NTHREADS + NTHREADS)
#define SMEM_BYTES (SMEM_FLOATS * sizeof(float))

extern "C" void kernel_launch(void* const* d_in, const int* in_sizes, int n_in,
                              void* d_out, int out_size)
{
    const float* query = (const float*)d_in[0];
    const float* facts = (const float*)d_in[1];
    const int*   mask  = (const int*)  d_in[2];
    const float* W1    = (const float*)d_in[3];
    const float* b1    = (const float*)d_in[4];
    const float* W2    = (const float*)d_in[5];
    const float* b2    = (const float*)d_in[6];
    const float* W3    = (const float*)d_in[7];
    const float* b3    = (const float*)d_in[8];
    float* out = (float*)d_out;

    int B = in_sizes[0] / E_DIM;

    cudaFuncSetAttribute(din_atten_kernel,
                         cudaFuncAttributeMaxDynamicSharedMemorySize,
                         (int)SMEM_BYTES);

    din_atten_kernel<<<B, NTHREADS, SMEM_BYTES>>>(query, facts, mask,
                                                  W1, b1, W2, b2, W3, b3, out);
}

// round 2
// speedup vs baseline: 1.2407x; 1.2407x over previous
#include <cuda_runtime.h>
#include <math.h>

#define T_LEN 200
#define E_DIM 64
#define H1 80
#define H2 40
#define NTHREADS 256

// strides chosen for conflict-free LDS.128 (odd in float4 units) and 16B alignment
#define FSH_STRIDE 68      // facts tile  [ROWS][68]
#define WEFF_STRIDE 68     // wefft [80][68]  (col-major: [col][e])
#define W2T_STRIDE 84      // w2t   [40][84]  (col-major: [col][k])

static __device__ float g_scores[2048 * T_LEN];

__device__ __forceinline__ float fast_sigmoid(float x) {
    return __fdividef(1.0f, 1.0f + __expf(-x));
}

// ============================================================================
// Kernel 1: per-batch row-tile score computation (fused MLP)
// NG row-groups of 32: ROWS = 32*NG.   grid = B, 256 threads, 2 CTAs/SM.
// ============================================================================
template <int NG>
__global__ __launch_bounds__(NTHREADS, 2)
void score_kernel(const float* __restrict__ query,
                  const float* __restrict__ facts,
                  const float* __restrict__ W1,
                  const float* __restrict__ b1,
                  const float* __restrict__ W2,
                  const float* __restrict__ b2,
                  const float* __restrict__ W3,
                  int row0)
{
    constexpr int ROWS = 32 * NG;
    constexpr int H1T_STRIDE = ROWS + 4;           // h1t [80][ROWS+4]

    extern __shared__ float sm[];
    float* fsh     = sm;                               // [ROWS][68]
    float* h1t     = fsh  + ROWS * FSH_STRIDE;         // [80][H1T_STRIDE]
    float* wefft   = h1t  + H1 * H1T_STRIDE;           // [80][68]
    float* w2t     = wefft + H1 * WEFF_STRIDE;         // [40][84]
    float* c1sh    = w2t  + H2 * W2T_STRIDE;           // [80]
    float* b2sh    = c1sh + H1;                        // [40]
    float* w3sh    = b2sh + H2;                        // [40]
    float* qsh     = w3sh + H2;                        // [64]
    float* scoresh = qsh  + E_DIM;                     // [ROWS]

    const int b   = blockIdx.x;
    const int tid = threadIdx.x;

    // ---------------- Phase 1: stage inputs ----------------
    if (tid < E_DIM) qsh[tid] = query[(size_t)b * E_DIM + tid];
    if (tid < H2)    { b2sh[tid] = b2[tid]; w3sh[tid] = W3[tid]; }
    if (tid < ROWS)  scoresh[tid] = 0.0f;

    // facts rows [row0, row0+ROWS), zero-pad beyond T_LEN
    {
        const float* fb = facts + ((size_t)b * T_LEN + row0) * E_DIM;
        for (int i = tid; i < ROWS * E_DIM; i += NTHREADS) {
            int t = i >> 6, e = i & 63;
            float v = (row0 + t < T_LEN) ? fb[t * E_DIM + e] : 0.0f;
            fsh[t * FSH_STRIDE + e] = v;
        }
    }
    // W2 transposed: w2t[col][k]
    for (int i = tid; i < H1 * H2; i += NTHREADS) {
        int k = i / H2, col = i - k * H2;              // i = k*40+col, coalesced gmem
        w2t[col * W2T_STRIDE + k] = W2[i];
    }
    __syncthreads();   // qsh ready before wefft

    // ---------------- Phase 2: per-batch effective layer-1 weights ----------------
    // din@W1 = q@(A+C) + f@(B-C) + (q*f)@D ; wefft[col][e] = (B-C)[e][col] + q[e]*D[e][col]
    for (int i = tid; i < E_DIM * H1; i += NTHREADS) {
        int e = i / H1, col = i - e * H1;              // coalesced gmem reads
        float wb = W1[ 5120 + i];                      // (64+e)*80+col
        float wc = W1[10240 + i];                      // (128+e)*80+col
        float wd = W1[15360 + i];                      // (192+e)*80+col
        wefft[col * WEFF_STRIDE + e] = wb - wc + qsh[e] * wd;
    }
    if (tid < H1) {
        float acc = b1[tid];
        #pragma unroll 8
        for (int e = 0; e < E_DIM; e++)
            acc += qsh[e] * (W1[e * H1 + tid] + W1[(2 * E_DIM + e) * H1 + tid]);
        c1sh[tid] = acc;
    }
    __syncthreads();

    const int tr = tid & 31;      // row lane
    const int tc = tid >> 5;      // warp id -> contiguous column group

    // ---------------- Phase 3: GEMM1  h1 = sigmoid(c1 + F @ Weff) ----------------
    {
        float acc[NG][10];
        #pragma unroll
        for (int i = 0; i < NG; i++)
            #pragma unroll
            for (int j = 0; j < 10; j++) acc[i][j] = 0.0f;

        #pragma unroll 1
        for (int e = 0; e < E_DIM; e += 4) {
            float4 fr[NG];
            #pragma unroll
            for (int i = 0; i < NG; i++)
                fr[i] = *(const float4*)&fsh[(tr + 32 * i) * FSH_STRIDE + e];
            #pragma unroll
            for (int j = 0; j < 10; j++) {
                float4 w = *(const float4*)&wefft[(tc * 10 + j) * WEFF_STRIDE + e];
                #pragma unroll
                for (int i = 0; i < NG; i++) {
                    acc[i][j] = fmaf(fr[i].x, w.x, acc[i][j]);
                    acc[i][j] = fmaf(fr[i].y, w.y, acc[i][j]);
                    acc[i][j] = fmaf(fr[i].z, w.z, acc[i][j]);
                    acc[i][j] = fmaf(fr[i].w, w.w, acc[i][j]);
                }
            }
        }
        #pragma unroll
        for (int j = 0; j < 10; j++) {
            int col = tc * 10 + j;
            float c1 = c1sh[col];
            #pragma unroll
            for (int i = 0; i < NG; i++)
                h1t[col * H1T_STRIDE + tr + 32 * i] = fast_sigmoid(acc[i][j] + c1);
        }
    }
    __syncthreads();

    // ---------------- Phase 4: GEMM2 + layer3 -> scores ----------------
    {
        float acc2[NG][5];
        #pragma unroll
        for (int i = 0; i < NG; i++)
            #pragma unroll
            for (int k = 0; k < 5; k++) acc2[i][k] = 0.0f;

        #pragma unroll 1
        for (int kk = 0; kk < H1; kk += 4) {
            float hr[NG][4];
            #pragma unroll
            for (int m = 0; m < 4; m++)
                #pragma unroll
                for (int i = 0; i < NG; i++)
                    hr[i][m] = h1t[(kk + m) * H1T_STRIDE + tr + 32 * i];
            #pragma unroll
            for (int k = 0; k < 5; k++) {
                float4 w = *(const float4*)&w2t[(tc * 5 + k) * W2T_STRIDE + kk];
                #pragma unroll
                for (int i = 0; i < NG; i++) {
                    acc2[i][k] = fmaf(hr[i][0], w.x, acc2[i][k]);
                    acc2[i][k] = fmaf(hr[i][1], w.y, acc2[i][k]);
                    acc2[i][k] = fmaf(hr[i][2], w.z, acc2[i][k]);
                    acc2[i][k] = fmaf(hr[i][3], w.w, acc2[i][k]);
                }
            }
        }
        #pragma unroll
        for (int i = 0; i < NG; i++) {
            float s = 0.0f;
            #pragma unroll
            for (int k = 0; k < 5; k++) {
                int col = tc * 5 + k;
                s += fast_sigmoid(acc2[i][k] + b2sh[col]) * w3sh[col];
            }
            atomicAdd(&scoresh[tr + 32 * i], s);
        }
    }
    __syncthreads();

    // write scores for active rows (b3 omitted: constant shift cancels in softmax)
    if (tid < ROWS && row0 + tid < T_LEN)
        g_scores[b * T_LEN + row0 + tid] = scoresh[tid];
}

// ============================================================================
// Kernel 2: masked softmax + attn-weighted fact sum. grid = B, 256 threads.
// ============================================================================
__global__ __launch_bounds__(NTHREADS)
void softmax_out_kernel(const float* __restrict__ facts,
                        const int*   __restrict__ mask,
                        float* __restrict__ out)
{
    __shared__ float attnsh[NTHREADS];
    __shared__ float red[NTHREADS];
    __shared__ float outred[NTHREADS];

    const int b   = blockIdx.x;
    const int tid = threadIdx.x;
    const float PADV = -4294967295.0f;   // -2^32 + 1

    float v;
    if (tid < T_LEN)
        v = (mask[(size_t)b * T_LEN + tid] == 1) ? g_scores[b * T_LEN + tid] : PADV;
    else
        v = -INFINITY;
    red[tid] = v;
    __syncthreads();
    #pragma unroll
    for (int off = 128; off > 0; off >>= 1) {
        if (tid < off) red[tid] = fmaxf(red[tid], red[tid + off]);
        __syncthreads();
    }
    float mmax = red[0];
    __syncthreads();
    float p = (tid < T_LEN) ? __expf(v - mmax) : 0.0f;
    red[tid] = p;
    __syncthreads();
    #pragma unroll
    for (int off = 128; off > 0; off >>= 1) {
        if (tid < off) red[tid] += red[tid + off];
        __syncthreads();
    }
    attnsh[tid] = p * (1.0f / red[0]);
    __syncthreads();

    // out[b][e] = sum_t attn[t] * facts[b][t][e], 4 t-chunks of 50
    {
        const int e = tid & 63;
        const int c = tid >> 6;
        const float* fb = facts + (size_t)b * T_LEN * E_DIM;
        float acc = 0.0f;
        const int t0 = c * 50;
        #pragma unroll 5
        for (int t = t0; t < t0 + 50; t++)
            acc = fmaf(attnsh[t], fb[t * E_DIM + e], acc);
        outred[c * 64 + e] = acc;
    }
    __syncthreads();
    if (tid < E_DIM)
        out[(size_t)b * E_DIM + tid] =
            outred[tid] + outred[64 + tid] + outred[128 + tid] + outred[192 + tid];
}

// ============================================================================
// launch
// ============================================================================
template <int NG>
static inline size_t score_smem_bytes() {
    constexpr int ROWS = 32 * NG;
    constexpr int H1T_STRIDE = ROWS + 4;
    size_t f = (size_t)ROWS * FSH_STRIDE + (size_t)H1 * H1T_STRIDE +
               (size_t)H1 * WEFF_STRIDE + (size_t)H2 * W2T_STRIDE +
               H1 + H2 + H2 + E_DIM + ROWS;
    return f * sizeof(float);
}

extern "C" void kernel_launch(void* const* d_in, const int* in_sizes, int n_in,
                              void* d_out, int out_size)
{
    const float* query = (const float*)d_in[0];
    const float* facts = (const float*)d_in[1];
    const int*   mask  = (const int*)  d_in[2];
    const float* W1    = (const float*)d_in[3];
    const float* b1    = (const float*)d_in[4];
    const float* W2    = (const float*)d_in[5];
    const float* b2    = (const float*)d_in[6];
    const float* W3    = (const float*)d_in[7];
    float* out = (float*)d_out;

    const int B = in_sizes[0] / E_DIM;

    static bool configured = false;
    if (!configured) {
        cudaFuncSetAttribute(score_kernel<4>,
                             cudaFuncAttributeMaxDynamicSharedMemorySize,
                             (int)score_smem_bytes<4>());
        cudaFuncSetAttribute(score_kernel<3>,
                             cudaFuncAttributeMaxDynamicSharedMemorySize,
                             (int)score_smem_bytes<3>());
        configured = true;
    }

    // rows [0,128)
    score_kernel<4><<<B, NTHREADS, score_smem_bytes<4>()>>>(
        query, facts, W1, b1, W2, b2, W3, 0);
    // rows [128, 224) -> active 128..199
    score_kernel<3><<<B, NTHREADS, score_smem_bytes<3>()>>>(
        query, facts, W1, b1, W2, b2, W3, 128);

    softmax_out_kernel<<<B, NTHREADS>>>(facts, mask, out);
}

// round 3
// speedup vs baseline: 1.3115x; 1.0571x over previous
#include <cuda_runtime.h>
#include <math.h>

#define T_LEN 200
#define E_DIM 64
#define H1 80
#define H2 40
#define NTHREADS 256

#define FSH_STRIDE 68      // facts tile [ROWS][68]; float4-granule conflict-free (17 odd)
#define WEFF_STRIDE 68     // wefft [80][68] col-major [col][e]
#define W2T_STRIDE 84      // w2t [40][84] col-major [col][k]; uniform loads
#define H1S 83             // h1 row-major [ROWS][83]; odd -> conflict-free scalar LDS/STS

static __device__ float g_scores[2048 * T_LEN];

__device__ __forceinline__ float fast_sigmoid(float x) {
    return __fdividef(1.0f, 1.0f + __expf(-x));
}

// packed fp32x2 FMA: d.lo += a.lo*b.lo ; d.hi += a.hi*b.hi (one instruction)
#define FMA2(acc, a, b) \
    asm("fma.rn.f32x2 %0, %1, %2, %0;" : "+l"(acc) : "l"(a), "l"(b))
#define PACK2(p, lo, hi) \
    asm("mov.b64 %0, {%1, %2};" : "=l"(p) : "f"(lo), "f"(hi))
#define UNPACK2(lo, hi, p) \
    asm("mov.b64 {%0, %1}, %2;" : "=f"(lo), "=f"(hi) : "l"(p))

// ============================================================================
// Kernel 1: per-batch row-tile score computation (fused MLP, f32x2 math)
// ============================================================================
template <int NG>
__global__ __launch_bounds__(NTHREADS, 2)
void score_kernel(const float* __restrict__ query,
                  const float* __restrict__ facts,
                  const float* __restrict__ W1,
                  const float* __restrict__ b1,
                  const float* __restrict__ W2,
                  const float* __restrict__ b2,
                  const float* __restrict__ W3,
                  int row0)
{
    constexpr int ROWS = 32 * NG;

    extern __shared__ float sm[];
    float* fsh     = sm;                               // [ROWS][68]
    float* h1sh    = fsh  + ROWS * FSH_STRIDE;         // [ROWS][83]
    float* wefft   = h1sh + ROWS * H1S;                // [80][68]
    float* w2t     = wefft + H1 * WEFF_STRIDE;         // [40][84]
    float* c1sh    = w2t  + H2 * W2T_STRIDE;           // [80]
    float* b2sh    = c1sh + H1;                        // [40]
    float* w3sh    = b2sh + H2;                        // [40]
    float* qsh     = w3sh + H2;                        // [64]
    float* scoresh = qsh  + E_DIM;                     // [ROWS]

    const int b   = blockIdx.x;
    const int tid = threadIdx.x;

    // ---------------- Phase 1: stage inputs ----------------
    if (tid < E_DIM) qsh[tid] = query[(size_t)b * E_DIM + tid];
    if (tid < H2)    { b2sh[tid] = b2[tid]; w3sh[tid] = W3[tid]; }
    if (tid < ROWS)  scoresh[tid] = 0.0f;

    {
        const float* fb = facts + ((size_t)b * T_LEN + row0) * E_DIM;
        for (int i = tid; i < ROWS * E_DIM; i += NTHREADS) {
            int t = i >> 6, e = i & 63;
            float v = (row0 + t < T_LEN) ? fb[t * E_DIM + e] : 0.0f;
            fsh[t * FSH_STRIDE + e] = v;
        }
    }
    for (int i = tid; i < H1 * H2; i += NTHREADS) {
        int k = i / H2, col = i - k * H2;              // coalesced gmem
        w2t[col * W2T_STRIDE + k] = W2[i];
    }
    __syncthreads();   // qsh ready

    // ---------------- Phase 2: per-batch effective layer-1 weights ----------------
    for (int i = tid; i < E_DIM * H1; i += NTHREADS) {
        int e = i / H1, col = i - e * H1;
        float wb = W1[ 5120 + i];
        float wc = W1[10240 + i];
        float wd = W1[15360 + i];
        wefft[col * WEFF_STRIDE + e] = wb - wc + qsh[e] * wd;
    }
    if (tid < H1) {
        float acc = b1[tid];
        #pragma unroll 8
        for (int e = 0; e < E_DIM; e++)
            acc += qsh[e] * (W1[e * H1 + tid] + W1[(2 * E_DIM + e) * H1 + tid]);
        c1sh[tid] = acc;
    }
    __syncthreads();

    const int tr = tid & 31;      // row lane
    const int tc = tid >> 5;      // warp id -> contiguous column group

    // ---------------- Phase 3: GEMM1  h1 = sigmoid(c1 + F @ Weff) ----------------
    // k-pair packed: acc.lo accumulates even-e terms, acc.hi odd-e terms.
    // j split into two halves of 5 to keep accumulator pairs at 40 regs.
    #pragma unroll
    for (int jh = 0; jh < 2; jh++) {
        const float* wbase = wefft + (tc * 10 + jh * 5) * WEFF_STRIDE;
        unsigned long long acc[NG][5];
        #pragma unroll
        for (int i = 0; i < NG; i++)
            #pragma unroll
            for (int j = 0; j < 5; j++) acc[i][j] = 0ull;

        #pragma unroll 1
        for (int e = 0; e < E_DIM; e += 4) {
            unsigned long long fr0[NG], fr1[NG];
            #pragma unroll
            for (int i = 0; i < NG; i++) {
                ulonglong2 v = *(const ulonglong2*)&fsh[(tr + 32 * i) * FSH_STRIDE + e];
                fr0[i] = v.x; fr1[i] = v.y;
            }
            #pragma unroll
            for (int j = 0; j < 5; j++) {
                ulonglong2 w = *(const ulonglong2*)&wbase[j * WEFF_STRIDE + e];
                #pragma unroll
                for (int i = 0; i < NG; i++) {
                    FMA2(acc[i][j], fr0[i], w.x);
                    FMA2(acc[i][j], fr1[i], w.y);
                }
            }
        }
        #pragma unroll
        for (int j = 0; j < 5; j++) {
            int col = tc * 10 + jh * 5 + j;
            float c1 = c1sh[col];
            #pragma unroll
            for (int i = 0; i < NG; i++) {
                float lo, hi; UNPACK2(lo, hi, acc[i][j]);
                h1sh[(tr + 32 * i) * H1S + col] = fast_sigmoid(lo + hi + c1);
            }
        }
    }
    __syncthreads();

    // ---------------- Phase 4: GEMM2 + layer3 -> scores ----------------
    {
        unsigned long long acc2[NG][5];
        #pragma unroll
        for (int i = 0; i < NG; i++)
            #pragma unroll
            for (int k = 0; k < 5; k++) acc2[i][k] = 0ull;

        #pragma unroll 1
        for (int kk = 0; kk < H1; kk += 4) {
            unsigned long long hp0[NG], hp1[NG];
            #pragma unroll
            for (int i = 0; i < NG; i++) {
                const float* hrow = &h1sh[(tr + 32 * i) * H1S + kk];
                PACK2(hp0[i], hrow[0], hrow[1]);
                PACK2(hp1[i], hrow[2], hrow[3]);
            }
            #pragma unroll
            for (int k = 0; k < 5; k++) {
                ulonglong2 w = *(const ulonglong2*)&w2t[(tc * 5 + k) * W2T_STRIDE + kk];
                #pragma unroll
                for (int i = 0; i < NG; i++) {
                    FMA2(acc2[i][k], hp0[i], w.x);
                    FMA2(acc2[i][k], hp1[i], w.y);
                }
            }
        }
        #pragma unroll
        for (int i = 0; i < NG; i++) {
            float s = 0.0f;
            #pragma unroll
            for (int k = 0; k < 5; k++) {
                int col = tc * 5 + k;
                float lo, hi; UNPACK2(lo, hi, acc2[i][k]);
                s += fast_sigmoid(lo + hi + b2sh[col]) * w3sh[col];
            }
            atomicAdd(&scoresh[tr + 32 * i], s);
        }
    }
    __syncthreads();

    // b3 omitted: constant shift cancels in softmax
    if (tid < ROWS && row0 + tid < T_LEN)
        g_scores[b * T_LEN + row0 + tid] = scoresh[tid];
}

// ============================================================================
// Kernel 2: masked softmax + attn-weighted fact sum
// ============================================================================
__global__ __launch_bounds__(NTHREADS)
void softmax_out_kernel(const float* __restrict__ facts,
                        const int*   __restrict__ mask,
                        float* __restrict__ out)
{
    __shared__ float attnsh[NTHREADS];
    __shared__ float red[NTHREADS];
    __shared__ float outred[NTHREADS];

    const int b   = blockIdx.x;
    const int tid = threadIdx.x;
    const float PADV = -4294967295.0f;   // -2^32 + 1

    float v;
    if (tid < T_LEN)
        v = (mask[(size_t)b * T_LEN + tid] == 1) ? g_scores[b * T_LEN + tid] : PADV;
    else
        v = -INFINITY;
    red[tid] = v;
    __syncthreads();
    #pragma unroll
    for (int off = 128; off > 0; off >>= 1) {
        if (tid < off) red[tid] = fmaxf(red[tid], red[tid + off]);
        __syncthreads();
    }
    float mmax = red[0];
    __syncthreads();
    float p = (tid < T_LEN) ? __expf(v - mmax) : 0.0f;
    red[tid] = p;
    __syncthreads();
    #pragma unroll
    for (int off = 128; off > 0; off >>= 1) {
        if (tid < off) red[tid] += red[tid + off];
        __syncthreads();
    }
    attnsh[tid] = p * (1.0f / red[0]);
    __syncthreads();

    {
        const int e = tid & 63;
        const int c = tid >> 6;
        const float* fb = facts + (size_t)b * T_LEN * E_DIM;
        float acc = 0.0f;
        const int t0 = c * 50;
        #pragma unroll 5
        for (int t = t0; t < t0 + 50; t++)
            acc = fmaf(attnsh[t], fb[t * E_DIM + e], acc);
        outred[c * 64 + e] = acc;
    }
    __syncthreads();
    if (tid < E_DIM)
        out[(size_t)b * E_DIM + tid] =
            outred[tid] + outred[64 + tid] + outred[128 + tid] + outred[192 + tid];
}

// ============================================================================
// launch
// ============================================================================
template <int NG>
static inline size_t score_smem_bytes() {
    constexpr int ROWS = 32 * NG;
    size_t f = (size_t)ROWS * FSH_STRIDE + (size_t)ROWS * H1S +
               (size_t)H1 * WEFF_STRIDE + (size_t)H2 * W2T_STRIDE +
               H1 + H2 + H2 + E_DIM + ROWS;
    return f * sizeof(float);
}

extern "C" void kernel_launch(void* const* d_in, const int* in_sizes, int n_in,
                              void* d_out, int out_size)
{
    const float* query = (const float*)d_in[0];
    const float* facts = (const float*)d_in[1];
    const int*   mask  = (const int*)  d_in[2];
    const float* W1    = (const float*)d_in[3];
    const float* b1    = (const float*)d_in[4];
    const float* W2    = (const float*)d_in[5];
    const float* b2    = (const float*)d_in[6];
    const float* W3    = (const float*)d_in[7];
    float* out = (float*)d_out;

    const int B = in_sizes[0] / E_DIM;

    static bool configured = false;
    if (!configured) {
        cudaFuncSetAttribute(score_kernel<4>,
                             cudaFuncAttributeMaxDynamicSharedMemorySize,
                             (int)score_smem_bytes<4>());
        cudaFuncSetAttribute(score_kernel<3>,
                             cudaFuncAttributeMaxDynamicSharedMemorySize,
                             (int)score_smem_bytes<3>());
        configured = true;
    }

    score_kernel<4><<<B, NTHREADS, score_smem_bytes<4>()>>>(
        query, facts, W1, b1, W2, b2, W3, 0);
    score_kernel<3><<<B, NTHREADS, score_smem_bytes<3>()>>>(
        query, facts, W1, b1, W2, b2, W3, 128);

    softmax_out_kernel<<<B, NTHREADS>>>(facts, mask, out);
}

// round 4
// speedup vs baseline: 1.8061x; 1.3771x over previous
#include <cuda_runtime.h>
#include <math.h>
#include <stdint.h>

#define T_LEN 200
#define E_DIM 64
#define H1 80
#define H2 40
#define NTHREADS 256

#define FS 68      // facts tile stride   [ROWS][68]
#define WS 68      // wefft stride        [80][68]   ([n][k])
#define HS 84      // h1 stride           [ROWS][84]
#define W2S 84     // w2t stride          [40][84]   ([n][k])

static __device__ float g_scores[2048 * T_LEN];

__device__ __forceinline__ float fast_sigmoid(float x) {
    return __fdividef(1.0f, 1.0f + __expf(-x));
}
__device__ __forceinline__ float tf32r(float f) {
    uint32_t u;
    asm("cvt.rna.tf32.f32 %0, %1;" : "=r"(u) : "f"(f));
    return __uint_as_float(u);
}
__device__ __forceinline__ void mma_tf32(float c[4], const uint32_t a[4], const uint32_t b[2]) {
    asm volatile(
        "mma.sync.aligned.m16n8k8.row.col.f32.tf32.tf32.f32 "
        "{%0,%1,%2,%3}, {%4,%5,%6,%7}, {%8,%9}, {%0,%1,%2,%3};"
        : "+f"(c[0]), "+f"(c[1]), "+f"(c[2]), "+f"(c[3])
        : "r"(a[0]), "r"(a[1]), "r"(a[2]), "r"(a[3]), "r"(b[0]), "r"(b[1]));
}

// ============================================================================
// Kernel 1: per-batch row-tile score computation, tensor-core MLP.
// NSTRIPES stripes of 16 rows; warp w owns stripe w. 256 thr, 2 CTAs/SM.
// ============================================================================
template <int NSTRIPES>
__global__ __launch_bounds__(NTHREADS, 2)
void score_kernel(const float* __restrict__ query,
                  const float* __restrict__ facts,
                  const float* __restrict__ W1,
                  const float* __restrict__ b1,
                  const float* __restrict__ W2,
                  const float* __restrict__ b2,
                  const float* __restrict__ W3,
                  int row0)
{
    constexpr int ROWS = 16 * NSTRIPES;

    extern __shared__ float sm[];
    float* fsh   = sm;                    // [ROWS][68]  (tf32-rounded)
    float* h1sh  = fsh  + ROWS * FS;      // [ROWS][84]  (tf32-rounded)
    float* wefft = h1sh + ROWS * HS;      // [80][68]    (tf32-rounded, [n][k])
    float* w2t   = wefft + H1 * WS;       // [40][84]    (tf32-rounded, [n][k])
    float* c1sh  = w2t  + H2 * W2S;       // [80]  fp32
    float* b2sh  = c1sh + H1;             // [40]  fp32
    float* w3sh  = b2sh + H2;             // [40]  fp32
    float* qsh   = w3sh + H2;             // [64]  fp32

    const int b    = blockIdx.x;
    const int tid  = threadIdx.x;
    const int w    = tid >> 5;
    const int lane = tid & 31;
    const int g    = lane >> 2;      // groupID
    const int tg   = lane & 3;       // thread-in-group

    // ---------------- Phase 1: stage inputs (tf32-rounded) ----------------
    if (tid < E_DIM) qsh[tid] = query[(size_t)b * E_DIM + tid];
    if (tid < H2)    { b2sh[tid] = b2[tid]; w3sh[tid] = W3[tid]; }

    {
        const float* fb = facts + ((size_t)b * T_LEN + row0) * E_DIM;
        for (int i = tid; i < ROWS * E_DIM; i += NTHREADS) {
            int t = i >> 6, e = i & 63;
            float v = (row0 + t < T_LEN) ? fb[t * E_DIM + e] : 0.0f;
            fsh[t * FS + e] = tf32r(v);
        }
    }
    for (int i = tid; i < H1 * H2; i += NTHREADS) {
        int k = i / H2, n = i - k * H2;            // coalesced gmem
        w2t[n * W2S + k] = tf32r(W2[i]);
    }
    __syncthreads();   // qsh ready

    // ---------------- Phase 2: per-batch effective layer-1 weights ----------------
    // din@W1 = q@(A+C) + f@(B-C) + (q*f)@D ; wefft[n][e] = (B-C)[e][n] + q[e]*D[e][n]
    for (int i = tid; i < E_DIM * H1; i += NTHREADS) {
        int e = i / H1, n = i - e * H1;
        float wb = W1[ 5120 + i];
        float wc = W1[10240 + i];
        float wd = W1[15360 + i];
        wefft[n * WS + e] = tf32r(wb - wc + qsh[e] * wd);
    }
    if (tid < H1) {
        float acc = b1[tid];
        #pragma unroll 8
        for (int e = 0; e < E_DIM; e++)
            acc += qsh[e] * (W1[e * H1 + tid] + W1[(2 * E_DIM + e) * H1 + tid]);
        c1sh[tid] = acc;
    }
    __syncthreads();

    const uint32_t* fu  = (const uint32_t*)fsh;
    const uint32_t* wu  = (const uint32_t*)wefft;
    const uint32_t* hu  = (const uint32_t*)h1sh;
    const uint32_t* w2u = (const uint32_t*)w2t;

    // ---------------- Phase 3: GEMM1  h1 = sigmoid(c1 + F @ Weff^T) ----------------
    if (w < NSTRIPES) {
        const int r0 = w * 16;
        float acc[10][4];
        #pragma unroll
        for (int j = 0; j < 10; j++)
            #pragma unroll
            for (int q = 0; q < 4; q++) acc[j][q] = 0.0f;

        #pragma unroll
        for (int kt = 0; kt < 8; kt++) {
            const int k0 = kt * 8 + tg;
            uint32_t a[4];
            a[0] = fu[(r0 + g    ) * FS + k0    ];
            a[1] = fu[(r0 + g + 8) * FS + k0    ];
            a[2] = fu[(r0 + g    ) * FS + k0 + 4];
            a[3] = fu[(r0 + g + 8) * FS + k0 + 4];
            #pragma unroll
            for (int j = 0; j < 10; j++) {
                uint32_t bf[2];
                bf[0] = wu[(j * 8 + g) * WS + k0    ];
                bf[1] = wu[(j * 8 + g) * WS + k0 + 4];
                mma_tf32(acc[j], a, bf);
            }
        }
        // epilogue: sigmoid + store to h1 (tf32-rounded)
        #pragma unroll
        for (int j = 0; j < 10; j++) {
            const int n0 = j * 8 + 2 * tg;
            float c1a = c1sh[n0], c1b = c1sh[n0 + 1];
            float2 lo = make_float2(tf32r(fast_sigmoid(acc[j][0] + c1a)),
                                    tf32r(fast_sigmoid(acc[j][1] + c1b)));
            float2 hi = make_float2(tf32r(fast_sigmoid(acc[j][2] + c1a)),
                                    tf32r(fast_sigmoid(acc[j][3] + c1b)));
            *(float2*)&h1sh[(r0 + g    ) * HS + n0] = lo;
            *(float2*)&h1sh[(r0 + g + 8) * HS + n0] = hi;
        }
    }
    __syncthreads();

    // ---------------- Phase 4: GEMM2 + layer3 -> scores ----------------
    if (w < NSTRIPES) {
        const int r0 = w * 16;
        float acc[5][4];
        #pragma unroll
        for (int j = 0; j < 5; j++)
            #pragma unroll
            for (int q = 0; q < 4; q++) acc[j][q] = 0.0f;

        #pragma unroll
        for (int kt = 0; kt < 10; kt++) {
            const int k0 = kt * 8 + tg;
            uint32_t a[4];
            a[0] = hu[(r0 + g    ) * HS + k0    ];
            a[1] = hu[(r0 + g + 8) * HS + k0    ];
            a[2] = hu[(r0 + g    ) * HS + k0 + 4];
            a[3] = hu[(r0 + g + 8) * HS + k0 + 4];
            #pragma unroll
            for (int j = 0; j < 5; j++) {
                uint32_t bf[2];
                bf[0] = w2u[(j * 8 + g) * W2S + k0    ];
                bf[1] = w2u[(j * 8 + g) * W2S + k0 + 4];
                mma_tf32(acc[j], a, bf);
            }
        }
        // epilogue: sigmoid, dot W3, quad-reduce, write scores
        float s_lo = 0.0f, s_hi = 0.0f;
        #pragma unroll
        for (int j = 0; j < 5; j++) {
            const int n0 = j * 8 + 2 * tg;
            float bb0 = b2sh[n0], bb1 = b2sh[n0 + 1];
            float w30 = w3sh[n0], w31 = w3sh[n0 + 1];
            s_lo += fast_sigmoid(acc[j][0] + bb0) * w30 +
                    fast_sigmoid(acc[j][1] + bb1) * w31;
            s_hi += fast_sigmoid(acc[j][2] + bb0) * w30 +
                    fast_sigmoid(acc[j][3] + bb1) * w31;
        }
        s_lo += __shfl_xor_sync(0xFFFFFFFF, s_lo, 1);
        s_lo += __shfl_xor_sync(0xFFFFFFFF, s_lo, 2);
        s_hi += __shfl_xor_sync(0xFFFFFFFF, s_hi, 1);
        s_hi += __shfl_xor_sync(0xFFFFFFFF, s_hi, 2);

        if (tg == 0) {   // b3 omitted: constant shift cancels in softmax
            int ra = row0 + r0 + g;
            int rb = ra + 8;
            if (ra < T_LEN) g_scores[b * T_LEN + ra] = s_lo;
            if (rb < T_LEN) g_scores[b * T_LEN + rb] = s_hi;
        }
    }
}

// ============================================================================
// Kernel 2: masked softmax + attn-weighted fact sum
// ============================================================================
__global__ __launch_bounds__(NTHREADS)
void softmax_out_kernel(const float* __restrict__ facts,
                        const int*   __restrict__ mask,
                        float* __restrict__ out)
{
    __shared__ float attnsh[NTHREADS];
    __shared__ float red[NTHREADS];
    __shared__ float outred[NTHREADS];

    const int b   = blockIdx.x;
    const int tid = threadIdx.x;
    const float PADV = -4294967295.0f;   // -2^32 + 1

    float v;
    if (tid < T_LEN)
        v = (mask[(size_t)b * T_LEN + tid] == 1) ? g_scores[b * T_LEN + tid] : PADV;
    else
        v = -INFINITY;
    red[tid] = v;
    __syncthreads();
    #pragma unroll
    for (int off = 128; off > 0; off >>= 1) {
        if (tid < off) red[tid] = fmaxf(red[tid], red[tid + off]);
        __syncthreads();
    }
    float mmax = red[0];
    __syncthreads();
    float p = (tid < T_LEN) ? __expf(v - mmax) : 0.0f;
    red[tid] = p;
    __syncthreads();
    #pragma unroll
    for (int off = 128; off > 0; off >>= 1) {
        if (tid < off) red[tid] += red[tid + off];
        __syncthreads();
    }
    attnsh[tid] = p * (1.0f / red[0]);
    __syncthreads();

    {
        const int e = tid & 63;
        const int c = tid >> 6;
        const float* fb = facts + (size_t)b * T_LEN * E_DIM;
        float acc = 0.0f;
        const int t0 = c * 50;
        #pragma unroll 5
        for (int t = t0; t < t0 + 50; t++)
            acc = fmaf(attnsh[t], fb[t * E_DIM + e], acc);
        outred[c * 64 + e] = acc;
    }
    __syncthreads();
    if (tid < E_DIM)
        out[(size_t)b * E_DIM + tid] =
            outred[tid] + outred[64 + tid] + outred[128 + tid] + outred[192 + tid];
}

// ============================================================================
// launch
// ============================================================================
template <int NSTRIPES>
static inline size_t score_smem_bytes() {
    constexpr int ROWS = 16 * NSTRIPES;
    size_t f = (size_t)ROWS * FS + (size_t)ROWS * HS +
               (size_t)H1 * WS + (size_t)H2 * W2S +
               H1 + H2 + H2 + E_DIM;
    return f * sizeof(float);
}

extern "C" void kernel_launch(void* const* d_in, const int* in_sizes, int n_in,
                              void* d_out, int out_size)
{
    const float* query = (const float*)d_in[0];
    const float* facts = (const float*)d_in[1];
    const int*   mask  = (const int*)  d_in[2];
    const float* W1    = (const float*)d_in[3];
    const float* b1    = (const float*)d_in[4];
    const float* W2    = (const float*)d_in[5];
    const float* b2    = (const float*)d_in[6];
    const float* W3    = (const float*)d_in[7];
    float* out = (float*)d_out;

    const int B = in_sizes[0] / E_DIM;

    static bool configured = false;
    if (!configured) {
        cudaFuncSetAttribute(score_kernel<8>,
                             cudaFuncAttributeMaxDynamicSharedMemorySize,
                             (int)score_smem_bytes<8>());
        cudaFuncSetAttribute(score_kernel<6>,
                             cudaFuncAttributeMaxDynamicSharedMemorySize,
                             (int)score_smem_bytes<6>());
        configured = true;
    }

    // rows [0,128)
    score_kernel<8><<<B, NTHREADS, score_smem_bytes<8>()>>>(
        query, facts, W1, b1, W2, b2, W3, 0);
    // rows [128,224) -> active 128..199
    score_kernel<6><<<B, NTHREADS, score_smem_bytes<6>()>>>(
        query, facts, W1, b1, W2, b2, W3, 128);

    softmax_out_kernel<<<B, NTHREADS>>>(facts, mask, out);
}

// round 5
// speedup vs baseline: 2.6251x; 1.4535x over previous
#include <cuda_runtime.h>
#include <math.h>
#include <stdint.h>

#define T_LEN 200
#define E_DIM 64
#define H1 80
#define H2 40
#define NTHREADS 256

#define FS 68      // facts tile stride [ROWS][68]; float4-granule conflict-free

static __device__ float g_scores[2048 * T_LEN];
static __device__ float g_wfrag[2048 * 5120];   // per-batch wefft, fragment-packed
static __device__ float g_c1[2048 * H1];
static __device__ float g_w2frag[3200];         // W2, fragment-packed (batch-invariant)

__device__ __forceinline__ float sigm(float x) {
    float t;
    asm("tanh.approx.f32 %0, %1;" : "=f"(t) : "f"(0.5f * x));
    return fmaf(0.5f, t, 0.5f);
}
__device__ __forceinline__ void mma_tf32(float c[4], const uint32_t a[4], const uint32_t b[2]) {
    asm volatile(
        "mma.sync.aligned.m16n8k8.row.col.f32.tf32.tf32.f32 "
        "{%0,%1,%2,%3}, {%4,%5,%6,%7}, {%8,%9}, {%0,%1,%2,%3};"
        : "+f"(c[0]), "+f"(c[1]), "+f"(c[2]), "+f"(c[3])
        : "r"(a[0]), "r"(a[1]), "r"(a[2]), "r"(a[3]), "r"(b[0]), "r"(b[1]));
}

// ============================================================================
// Prologue: per-batch effective layer-1 weights (fragment-packed) + c1.
// CTA 0 additionally fragment-packs W2.
// Fragment order (GEMM1): pair index fp = kt*320 + j*32 + lane, lane = g*4+tg,
//   value pair = wefft[n=j*8+g][k=kt*8+tg], wefft[n][k+4]
// ============================================================================
__global__ __launch_bounds__(NTHREADS)
void prep_kernel(const float* __restrict__ query,
                 const float* __restrict__ W1,
                 const float* __restrict__ b1,
                 const float* __restrict__ W2)
{
    __shared__ float qsh[E_DIM];
    const int b   = blockIdx.x;
    const int tid = threadIdx.x;

    if (tid < E_DIM) qsh[tid] = query[(size_t)b * E_DIM + tid];
    __syncthreads();

    // wefft[n][k] = W1[(64+k)*80+n] - W1[(128+k)*80+n] + q[k]*W1[(192+k)*80+n]
    float2* wout = (float2*)(g_wfrag + (size_t)b * 5120);
    for (int fp = tid; fp < 2560; fp += NTHREADS) {
        int kt = fp / 320, rem = fp - kt * 320;
        int j = rem >> 5, lane = rem & 31;
        int g = lane >> 2, tg = lane & 3;
        int n = j * 8 + g;
        int ka = kt * 8 + tg, kb = ka + 4;
        float va = W1[(64 + ka) * H1 + n] - W1[(128 + ka) * H1 + n] + qsh[ka] * W1[(192 + ka) * H1 + n];
        float vb = W1[(64 + kb) * H1 + n] - W1[(128 + kb) * H1 + n] + qsh[kb] * W1[(192 + kb) * H1 + n];
        wout[fp] = make_float2(va, vb);
    }
    if (tid < H1) {
        float acc = b1[tid];
        #pragma unroll 8
        for (int e = 0; e < E_DIM; e++)
            acc += qsh[e] * (W1[e * H1 + tid] + W1[(128 + e) * H1 + tid]);
        g_c1[b * H1 + tid] = acc;
    }
    // W2 fragments (GEMM2): fp = kt*160 + j*32 + lane; pair = W2T[n=j*8+g][k=kt*8+tg], [k+4]
    if (b == 0) {
        float2* w2out = (float2*)g_w2frag;
        for (int fp = tid; fp < 1600; fp += NTHREADS) {
            int kt = fp / 160, rem = fp - kt * 160;
            int j = rem >> 5, lane = rem & 31;
            int g = lane >> 2, tg = lane & 3;
            int n = j * 8 + g;
            int ka = kt * 8 + tg;
            w2out[fp] = make_float2(W2[ka * H2 + n], W2[(ka + 4) * H2 + n]);
        }
    }
}

// ============================================================================
// Score kernel: tensor-core MLP, h1 kept in registers (shfl exchange).
// ============================================================================
template <int NSTRIPES>
__global__ __launch_bounds__(NTHREADS, 2)
void score_kernel(const float* __restrict__ facts,
                  const float* __restrict__ b2,
                  const float* __restrict__ W3,
                  int row0)
{
    constexpr int ROWS = 16 * NSTRIPES;

    extern __shared__ float sm[];
    float* fsh  = sm;                 // [ROWS][68] fp32 (HW truncates in mma)
    float* wfr  = fsh + ROWS * FS;    // [5120] fragment-packed wefft
    float* w2fr = wfr + 5120;         // [3200] fragment-packed W2
    float* c1sh = w2fr + 3200;        // [80]
    float* b2sh = c1sh + H1;          // [40]
    float* w3sh = b2sh + H2;          // [40]

    const int b    = blockIdx.x;
    const int tid  = threadIdx.x;
    const int w    = tid >> 5;
    const int lane = tid & 31;
    const int g    = lane >> 2;
    const int tg   = lane & 3;

    // ---------------- staging: pure vector copies ----------------
    {
        const float4* fb = (const float4*)(facts + ((size_t)b * T_LEN + row0) * E_DIM);
        const float4 z = make_float4(0.f, 0.f, 0.f, 0.f);
        for (int i = tid; i < ROWS * 16; i += NTHREADS) {
            int t = i >> 4, e4 = i & 15;
            float4 v = (row0 + t < T_LEN) ? fb[t * 16 + e4] : z;
            *(float4*)&fsh[t * FS + e4 * 4] = v;
        }
    }
    {
        const float4* src = (const float4*)(g_wfrag + (size_t)b * 5120);
        float4* dst = (float4*)wfr;
        for (int i = tid; i < 1280; i += NTHREADS) dst[i] = src[i];
    }
    {
        const float4* src = (const float4*)g_w2frag;
        float4* dst = (float4*)w2fr;
        for (int i = tid; i < 800; i += NTHREADS) dst[i] = src[i];
    }
    if (tid < H1) c1sh[tid] = g_c1[b * H1 + tid];
    if (tid < H2) { b2sh[tid] = b2[tid]; w3sh[tid] = W3[tid]; }
    __syncthreads();

    if (w >= NSTRIPES) return;
    const int r0 = w * 16;
    const uint32_t* fu = (const uint32_t*)fsh;

    // ---------------- GEMM1: acc = F @ Weff^T ----------------
    float acc[10][4];
    #pragma unroll
    for (int j = 0; j < 10; j++)
        #pragma unroll
        for (int q = 0; q < 4; q++) acc[j][q] = 0.0f;

    #pragma unroll
    for (int kt = 0; kt < 8; kt++) {
        const int k0 = kt * 8 + tg;
        uint32_t a[4];
        a[0] = fu[(r0 + g    ) * FS + k0    ];
        a[1] = fu[(r0 + g + 8) * FS + k0    ];
        a[2] = fu[(r0 + g    ) * FS + k0 + 4];
        a[3] = fu[(r0 + g + 8) * FS + k0 + 4];
        const float2* wp = (const float2*)wfr + kt * 320 + lane;
        #pragma unroll
        for (int j = 0; j < 10; j++) {
            float2 bw = wp[j * 32];
            uint32_t bf[2] = { __float_as_uint(bw.x), __float_as_uint(bw.y) };
            mma_tf32(acc[j], a, bf);
        }
    }

    // ---------------- fused sigmoid + shfl-exchange + GEMM2 ----------------
    float acc2[5][4];
    #pragma unroll
    for (int j = 0; j < 5; j++)
        #pragma unroll
        for (int q = 0; q < 4; q++) acc2[j][q] = 0.0f;

    const int src_lo = (g << 2) + (tg >> 1);
    const int src_hi = src_lo + 2;
    const bool odd = (tg & 1);

    #pragma unroll
    for (int kt = 0; kt < 10; kt++) {        // phase-3 j == phase-4 kt
        const int n0 = kt * 8 + 2 * tg;
        float c1a = c1sh[n0], c1b = c1sh[n0 + 1];
        float s0 = sigm(acc[kt][0] + c1a);   // (row g,   col n0)
        float s1 = sigm(acc[kt][1] + c1b);   // (row g,   col n0+1)
        float s2 = sigm(acc[kt][2] + c1a);   // (row g+8, col n0)
        float s3 = sigm(acc[kt][3] + c1b);   // (row g+8, col n0+1)

        // A-fragment for phase 4: rows g/g+8, cols kt*8+tg and +4
        float v0 = __shfl_sync(0xFFFFFFFF, s0, src_lo);
        float v1 = __shfl_sync(0xFFFFFFFF, s1, src_lo);
        float a0 = odd ? v1 : v0;
        v0 = __shfl_sync(0xFFFFFFFF, s2, src_lo);
        v1 = __shfl_sync(0xFFFFFFFF, s3, src_lo);
        float a1 = odd ? v1 : v0;
        v0 = __shfl_sync(0xFFFFFFFF, s0, src_hi);
        v1 = __shfl_sync(0xFFFFFFFF, s1, src_hi);
        float a2 = odd ? v1 : v0;
        v0 = __shfl_sync(0xFFFFFFFF, s2, src_hi);
        v1 = __shfl_sync(0xFFFFFFFF, s3, src_hi);
        float a3 = odd ? v1 : v0;

        uint32_t a[4] = { __float_as_uint(a0), __float_as_uint(a1),
                          __float_as_uint(a2), __float_as_uint(a3) };
        const float2* wp = (const float2*)w2fr + kt * 160 + lane;
        #pragma unroll
        for (int j = 0; j < 5; j++) {
            float2 bw = wp[j * 32];
            uint32_t bf[2] = { __float_as_uint(bw.x), __float_as_uint(bw.y) };
            mma_tf32(acc2[j], a, bf);
        }
    }

    // ---------------- epilogue: sigmoid, dot W3, quad-reduce, write ----------------
    float s_lo = 0.0f, s_hi = 0.0f;
    #pragma unroll
    for (int j = 0; j < 5; j++) {
        const int n0 = j * 8 + 2 * tg;
        float bb0 = b2sh[n0], bb1 = b2sh[n0 + 1];
        float w30 = w3sh[n0], w31 = w3sh[n0 + 1];
        s_lo += sigm(acc2[j][0] + bb0) * w30 + sigm(acc2[j][1] + bb1) * w31;
        s_hi += sigm(acc2[j][2] + bb0) * w30 + sigm(acc2[j][3] + bb1) * w31;
    }
    s_lo += __shfl_xor_sync(0xFFFFFFFF, s_lo, 1);
    s_lo += __shfl_xor_sync(0xFFFFFFFF, s_lo, 2);
    s_hi += __shfl_xor_sync(0xFFFFFFFF, s_hi, 1);
    s_hi += __shfl_xor_sync(0xFFFFFFFF, s_hi, 2);

    if (tg == 0) {   // b3 omitted: constant shift cancels in softmax
        int ra = row0 + r0 + g;
        int rb = ra + 8;
        if (ra < T_LEN) g_scores[b * T_LEN + ra] = s_lo;
        if (rb < T_LEN) g_scores[b * T_LEN + rb] = s_hi;
    }
}

// ============================================================================
// Kernel 2: masked softmax + attn-weighted fact sum
// ============================================================================
__global__ __launch_bounds__(NTHREADS)
void softmax_out_kernel(const float* __restrict__ facts,
                        const int*   __restrict__ mask,
                        float* __restrict__ out)
{
    __shared__ float attnsh[NTHREADS];
    __shared__ float red[NTHREADS];
    __shared__ float outred[NTHREADS];

    const int b   = blockIdx.x;
    const int tid = threadIdx.x;
    const float PADV = -4294967295.0f;   // -2^32 + 1

    float v;
    if (tid < T_LEN)
        v = (mask[(size_t)b * T_LEN + tid] == 1) ? g_scores[b * T_LEN + tid] : PADV;
    else
        v = -INFINITY;
    red[tid] = v;
    __syncthreads();
    #pragma unroll
    for (int off = 128; off > 0; off >>= 1) {
        if (tid < off) red[tid] = fmaxf(red[tid], red[tid + off]);
        __syncthreads();
    }
    float mmax = red[0];
    __syncthreads();
    float p = (tid < T_LEN) ? __expf(v - mmax) : 0.0f;
    red[tid] = p;
    __syncthreads();
    #pragma unroll
    for (int off = 128; off > 0; off >>= 1) {
        if (tid < off) red[tid] += red[tid + off];
        __syncthreads();
    }
    attnsh[tid] = p * (1.0f / red[0]);
    __syncthreads();

    {
        const int e = tid & 63;
        const int c = tid >> 6;
        const float* fb = facts + (size_t)b * T_LEN * E_DIM;
        float acc = 0.0f;
        const int t0 = c * 50;
        #pragma unroll 5
        for (int t = t0; t < t0 + 50; t++)
            acc = fmaf(attnsh[t], fb[t * E_DIM + e], acc);
        outred[c * 64 + e] = acc;
    }
    __syncthreads();
    if (tid < E_DIM)
        out[(size_t)b * E_DIM + tid] =
            outred[tid] + outred[64 + tid] + outred[128 + tid] + outred[192 + tid];
}

// ============================================================================
// launch
// ============================================================================
template <int NSTRIPES>
static inline size_t score_smem_bytes() {
    constexpr int ROWS = 16 * NSTRIPES;
    size_t f = (size_t)ROWS * FS + 5120 + 3200 + H1 + H2 + H2;
    return f * sizeof(float);
}

extern "C" void kernel_launch(void* const* d_in, const int* in_sizes, int n_in,
                              void* d_out, int out_size)
{
    const float* query = (const float*)d_in[0];
    const float* facts = (const float*)d_in[1];
    const int*   mask  = (const int*)  d_in[2];
    const float* W1    = (const float*)d_in[3];
    const float* b1    = (const float*)d_in[4];
    const float* W2    = (const float*)d_in[5];
    const float* b2    = (const float*)d_in[6];
    const float* W3    = (const float*)d_in[7];
    float* out = (float*)d_out;

    const int B = in_sizes[0] / E_DIM;

    static bool configured = false;
    if (!configured) {
        cudaFuncSetAttribute(score_kernel<8>,
                             cudaFuncAttributeMaxDynamicSharedMemorySize,
                             (int)score_smem_bytes<8>());
        cudaFuncSetAttribute(score_kernel<6>,
                             cudaFuncAttributeMaxDynamicSharedMemorySize,
                             (int)score_smem_bytes<6>());
        configured = true;
    }

    prep_kernel<<<B, NTHREADS>>>(query, W1, b1, W2);
    score_kernel<8><<<B, NTHREADS, score_smem_bytes<8>()>>>(facts, b2, W3, 0);
    score_kernel<6><<<B, NTHREADS, score_smem_bytes<6>()>>>(facts, b2, W3, 128);
    softmax_out_kernel<<<B, NTHREADS>>>(facts, mask, out);
}

// round 6
// speedup vs baseline: 3.0548x; 1.1637x over previous
#include <cuda_runtime.h>
#include <math.h>
#include <stdint.h>

#define T_LEN 200
#define E_DIM 64
#define H1 80
#define H2 40
#define NTHREADS 256
#define NSTRIPES 14        // 224 rows = 14 * 16
#define ROWS (16 * NSTRIPES)

#define FS 68              // facts tile stride [224][68]; float4-granule conflict-free

static __device__ float g_wfrag[2048 * 5120];   // per-batch wefft, fragment-packed
static __device__ float g_c1[2048 * H1];
static __device__ float g_w2frag[3200];         // W2, fragment-packed (batch-invariant)

__device__ __forceinline__ float sigm(float x) {
    float t;
    asm("tanh.approx.f32 %0, %1;" : "=f"(t) : "f"(0.5f * x));
    return fmaf(0.5f, t, 0.5f);
}
__device__ __forceinline__ void mma_tf32(float c[4], const uint32_t a[4], const uint32_t b[2]) {
    asm volatile(
        "mma.sync.aligned.m16n8k8.row.col.f32.tf32.tf32.f32 "
        "{%0,%1,%2,%3}, {%4,%5,%6,%7}, {%8,%9}, {%0,%1,%2,%3};"
        : "+f"(c[0]), "+f"(c[1]), "+f"(c[2]), "+f"(c[3])
        : "r"(a[0]), "r"(a[1]), "r"(a[2]), "r"(a[3]), "r"(b[0]), "r"(b[1]));
}

// ============================================================================
// Prologue: per-batch effective layer-1 weights (fragment-packed) + c1.
// CTA 0 additionally fragment-packs W2.
// ============================================================================
__global__ __launch_bounds__(NTHREADS)
void prep_kernel(const float* __restrict__ query,
                 const float* __restrict__ W1,
                 const float* __restrict__ b1,
                 const float* __restrict__ W2)
{
    __shared__ float qsh[E_DIM];
    const int b   = blockIdx.x;
    const int tid = threadIdx.x;

    if (tid < E_DIM) qsh[tid] = query[(size_t)b * E_DIM + tid];
    __syncthreads();

    // wefft[n][k] = W1[(64+k)*80+n] - W1[(128+k)*80+n] + q[k]*W1[(192+k)*80+n]
    float2* wout = (float2*)(g_wfrag + (size_t)b * 5120);
    for (int fp = tid; fp < 2560; fp += NTHREADS) {
        int kt = fp / 320, rem = fp - kt * 320;
        int j = rem >> 5, lane = rem & 31;
        int g = lane >> 2, tg = lane & 3;
        int n = j * 8 + g;
        int ka = kt * 8 + tg, kb = ka + 4;
        float va = W1[(64 + ka) * H1 + n] - W1[(128 + ka) * H1 + n] + qsh[ka] * W1[(192 + ka) * H1 + n];
        float vb = W1[(64 + kb) * H1 + n] - W1[(128 + kb) * H1 + n] + qsh[kb] * W1[(192 + kb) * H1 + n];
        wout[fp] = make_float2(va, vb);
    }
    if (tid < H1) {
        float acc = b1[tid];
        #pragma unroll 8
        for (int e = 0; e < E_DIM; e++)
            acc += qsh[e] * (W1[e * H1 + tid] + W1[(128 + e) * H1 + tid]);
        g_c1[b * H1 + tid] = acc;
    }
    if (b == 0) {
        float2* w2out = (float2*)g_w2frag;
        for (int fp = tid; fp < 1600; fp += NTHREADS) {
            int kt = fp / 160, rem = fp - kt * 160;
            int j = rem >> 5, lane = rem & 31;
            int g = lane >> 2, tg = lane & 3;
            int n = j * 8 + g;
            int ka = kt * 8 + tg;
            w2out[fp] = make_float2(W2[ka * H2 + n], W2[(ka + 4) * H2 + n]);
        }
    }
}

// ============================================================================
// Fused kernel: MLP scores (tensor cores) + masked softmax + weighted sum.
// One CTA per batch. Facts read from HBM exactly once.
// ============================================================================
__global__ __launch_bounds__(NTHREADS, 2)
void fused_kernel(const float* __restrict__ facts,
                  const int*   __restrict__ mask,
                  const float* __restrict__ b2,
                  const float* __restrict__ W3,
                  float* __restrict__ out)
{
    extern __shared__ float sm[];
    float* fsh     = sm;                  // [224][68] fp32
    float* wfr     = fsh + ROWS * FS;     // [5120] fragment-packed wefft
    float* w2fr    = wfr + 5120;          // [3200] fragment-packed W2
    float* c1sh    = w2fr + 3200;         // [80]
    float* b2sh    = c1sh + H1;           // [40]
    float* w3sh    = b2sh + H2;           // [40]
    float* scoresh = w3sh + H2;           // [224]
    float* red     = scoresh + ROWS;      // [256]
    float* attnsh  = red + NTHREADS;      // [224]
    float* outred  = attnsh + ROWS;       // [256]

    const int b    = blockIdx.x;
    const int tid  = threadIdx.x;
    const int w    = tid >> 5;
    const int lane = tid & 31;
    const int g    = lane >> 2;
    const int tg   = lane & 3;

    // ---------------- staging: pure vector copies ----------------
    {
        const float4* fb = (const float4*)(facts + (size_t)b * T_LEN * E_DIM);
        const float4 z = make_float4(0.f, 0.f, 0.f, 0.f);
        for (int i = tid; i < ROWS * 16; i += NTHREADS) {
            int t = i >> 4, e4 = i & 15;
            float4 v = (t < T_LEN) ? fb[t * 16 + e4] : z;
            *(float4*)&fsh[t * FS + e4 * 4] = v;
        }
    }
    {
        const float4* src = (const float4*)(g_wfrag + (size_t)b * 5120);
        float4* dst = (float4*)wfr;
        for (int i = tid; i < 1280; i += NTHREADS) dst[i] = src[i];
    }
    {
        const float4* src = (const float4*)g_w2frag;
        float4* dst = (float4*)w2fr;
        for (int i = tid; i < 800; i += NTHREADS) dst[i] = src[i];
    }
    if (tid < H1) c1sh[tid] = g_c1[b * H1 + tid];
    if (tid < H2) { b2sh[tid] = b2[tid]; w3sh[tid] = W3[tid]; }
    __syncthreads();

    const uint32_t* fu = (const uint32_t*)fsh;

    // ---------------- per-stripe MLP (warp w handles stripes w, w+8) ----------------
    for (int s = w; s < NSTRIPES; s += 8) {
        const int r0 = s * 16;

        // GEMM1: acc = F @ Weff^T
        float acc[10][4];
        #pragma unroll
        for (int j = 0; j < 10; j++)
            #pragma unroll
            for (int q = 0; q < 4; q++) acc[j][q] = 0.0f;

        #pragma unroll
        for (int kt = 0; kt < 8; kt++) {
            const int k0 = kt * 8 + tg;
            uint32_t a[4];
            a[0] = fu[(r0 + g    ) * FS + k0    ];
            a[1] = fu[(r0 + g + 8) * FS + k0    ];
            a[2] = fu[(r0 + g    ) * FS + k0 + 4];
            a[3] = fu[(r0 + g + 8) * FS + k0 + 4];
            const float2* wp = (const float2*)wfr + kt * 320 + lane;
            #pragma unroll
            for (int j = 0; j < 10; j++) {
                float2 bw = wp[j * 32];
                uint32_t bf[2] = { __float_as_uint(bw.x), __float_as_uint(bw.y) };
                mma_tf32(acc[j], a, bf);
            }
        }

        // fused sigmoid + shfl-exchange + GEMM2
        float acc2[5][4];
        #pragma unroll
        for (int j = 0; j < 5; j++)
            #pragma unroll
            for (int q = 0; q < 4; q++) acc2[j][q] = 0.0f;

        const int src_lo = (g << 2) + (tg >> 1);
        const int src_hi = src_lo + 2;
        const bool odd = (tg & 1);

        #pragma unroll
        for (int kt = 0; kt < 10; kt++) {
            const int n0 = kt * 8 + 2 * tg;
            float c1a = c1sh[n0], c1b = c1sh[n0 + 1];
            float s0 = sigm(acc[kt][0] + c1a);
            float s1 = sigm(acc[kt][1] + c1b);
            float s2 = sigm(acc[kt][2] + c1a);
            float s3 = sigm(acc[kt][3] + c1b);

            float v0 = __shfl_sync(0xFFFFFFFF, s0, src_lo);
            float v1 = __shfl_sync(0xFFFFFFFF, s1, src_lo);
            float a0 = odd ? v1 : v0;
            v0 = __shfl_sync(0xFFFFFFFF, s2, src_lo);
            v1 = __shfl_sync(0xFFFFFFFF, s3, src_lo);
            float a1 = odd ? v1 : v0;
            v0 = __shfl_sync(0xFFFFFFFF, s0, src_hi);
            v1 = __shfl_sync(0xFFFFFFFF, s1, src_hi);
            float a2 = odd ? v1 : v0;
            v0 = __shfl_sync(0xFFFFFFFF, s2, src_hi);
            v1 = __shfl_sync(0xFFFFFFFF, s3, src_hi);
            float a3 = odd ? v1 : v0;

            uint32_t a[4] = { __float_as_uint(a0), __float_as_uint(a1),
                              __float_as_uint(a2), __float_as_uint(a3) };
            const float2* wp = (const float2*)w2fr + kt * 160 + lane;
            #pragma unroll
            for (int j = 0; j < 5; j++) {
                float2 bw = wp[j * 32];
                uint32_t bf[2] = { __float_as_uint(bw.x), __float_as_uint(bw.y) };
                mma_tf32(acc2[j], a, bf);
            }
        }

        // epilogue: sigmoid, dot W3, quad-reduce, write scores to smem
        float s_lo = 0.0f, s_hi = 0.0f;
        #pragma unroll
        for (int j = 0; j < 5; j++) {
            const int n0 = j * 8 + 2 * tg;
            float bb0 = b2sh[n0], bb1 = b2sh[n0 + 1];
            float w30 = w3sh[n0], w31 = w3sh[n0 + 1];
            s_lo += sigm(acc2[j][0] + bb0) * w30 + sigm(acc2[j][1] + bb1) * w31;
            s_hi += sigm(acc2[j][2] + bb0) * w30 + sigm(acc2[j][3] + bb1) * w31;
        }
        s_lo += __shfl_xor_sync(0xFFFFFFFF, s_lo, 1);
        s_lo += __shfl_xor_sync(0xFFFFFFFF, s_lo, 2);
        s_hi += __shfl_xor_sync(0xFFFFFFFF, s_hi, 1);
        s_hi += __shfl_xor_sync(0xFFFFFFFF, s_hi, 2);

        if (tg == 0) {   // b3 omitted: constant shift cancels in softmax
            scoresh[r0 + g]     = s_lo;
            scoresh[r0 + g + 8] = s_hi;
        }
    }
    __syncthreads();

    // ---------------- masked softmax over T ----------------
    const float PADV = -4294967295.0f;   // -2^32 + 1
    float v;
    if (tid < T_LEN)
        v = (mask[(size_t)b * T_LEN + tid] == 1) ? scoresh[tid] : PADV;
    else
        v = -INFINITY;
    red[tid] = v;
    __syncthreads();
    #pragma unroll
    for (int off = 128; off > 0; off >>= 1) {
        if (tid < off) red[tid] = fmaxf(red[tid], red[tid + off]);
        __syncthreads();
    }
    float mmax = red[0];
    __syncthreads();
    float p = (tid < T_LEN) ? __expf(v - mmax) : 0.0f;
    red[tid] = p;
    __syncthreads();
    #pragma unroll
    for (int off = 128; off > 0; off >>= 1) {
        if (tid < off) red[tid] += red[tid + off];
        __syncthreads();
    }
    float inv = 1.0f / red[0];
    attnsh[tid] = p * inv;                     // tids >= T_LEN contribute 0
    if (tid < ROWS - NTHREADS + 32) { }        // (no-op; ROWS-T pad below)
    if (tid + NTHREADS < ROWS) attnsh[tid + NTHREADS] = 0.0f;
    __syncthreads();

    // ---------------- out[b] = attn @ facts (smem-resident) ----------------
    {
        const int e = tid & 63;
        const int c = tid >> 6;                // 4 chunks of 56 rows (224 total)
        float acc = 0.0f;
        const int t0 = c * 56;
        #pragma unroll 7
        for (int t = t0; t < t0 + 56; t++)
            acc = fmaf(attnsh[t], fsh[t * FS + e], acc);
        outred[c * 64 + e] = acc;
    }
    __syncthreads();
    if (tid < E_DIM)
        out[(size_t)b * E_DIM + tid] =
            outred[tid] + outred[64 + tid] + outred[128 + tid] + outred[192 + tid];
}

// ============================================================================
// launch
// ============================================================================
static inline size_t fused_smem_bytes() {
    size_t f = (size_t)ROWS * FS + 5120 + 3200 + H1 + H2 + H2 +
               ROWS + NTHREADS + ROWS + NTHREADS;
    return f * sizeof(float);
}

extern "C" void kernel_launch(void* const* d_in, const int* in_sizes, int n_in,
                              void* d_out, int out_size)
{
    const float* query = (const float*)d_in[0];
    const float* facts = (const float*)d_in[1];
    const int*   mask  = (const int*)  d_in[2];
    const float* W1    = (const float*)d_in[3];
    const float* b1    = (const float*)d_in[4];
    const float* W2    = (const float*)d_in[5];
    const float* b2    = (const float*)d_in[6];
    const float* W3    = (const float*)d_in[7];
    float* out = (float*)d_out;

    const int B = in_sizes[0] / E_DIM;

    static bool configured = false;
    if (!configured) {
        cudaFuncSetAttribute(fused_kernel,
                             cudaFuncAttributeMaxDynamicSharedMemorySize,
                             (int)fused_smem_bytes());
        configured = true;
    }

    prep_kernel<<<B, NTHREADS>>>(query, W1, b1, W2);
    fused_kernel<<<B, NTHREADS, fused_smem_bytes()>>>(facts, mask, b2, W3, out);
}

// round 8
// speedup vs baseline: 4.0723x; 1.3331x over previous
#include <cuda_runtime.h>
#include <math.h>
#include <stdint.h>

#define T_LEN 200
#define E_DIM 64
#define H1 80
#define H2 40
#define NTHREADS 256
#define NSTRIPES 13        // 208 rows = 13 * 16 (covers T=200)
#define ROWS (16 * NSTRIPES)

#define FS 68              // facts tile stride [208][68]; float4-granule conflict-free

__device__ __forceinline__ float sigm(float x) {
    float t;
    asm("tanh.approx.f32 %0, %1;" : "=f"(t) : "f"(0.5f * x));
    return fmaf(0.5f, t, 0.5f);
}
__device__ __forceinline__ void mma_tf32(float c[4], const uint32_t a[4], const uint32_t b[2]) {
    asm volatile(
        "mma.sync.aligned.m16n8k8.row.col.f32.tf32.tf32.f32 "
        "{%0,%1,%2,%3}, {%4,%5,%6,%7}, {%8,%9}, {%0,%1,%2,%3};"
        : "+f"(c[0]), "+f"(c[1]), "+f"(c[2]), "+f"(c[3])
        : "r"(a[0]), "r"(a[1]), "r"(a[2]), "r"(a[3]), "r"(b[0]), "r"(b[1]));
}
__device__ __forceinline__ void cp_async16(uint32_t smem_addr, const void* gptr) {
    asm volatile("cp.async.cg.shared.global [%0], [%1], 16;" :: "r"(smem_addr), "l"(gptr));
}

// ============================================================================
// Single fused kernel: staging + per-batch weight transform + tensor-core MLP
// + masked softmax + attn-weighted sum. One CTA per batch.
// ============================================================================
__global__ __launch_bounds__(NTHREADS, 2)
void fused_kernel(const float* __restrict__ query,
                  const float* __restrict__ facts,
                  const int*   __restrict__ mask,
                  const float* __restrict__ W1,
                  const float* __restrict__ b1,
                  const float* __restrict__ W2,
                  const float* __restrict__ b2,
                  const float* __restrict__ W3,
                  float* __restrict__ out)
{
    extern __shared__ float sm[];
    float* fsh     = sm;                  // [208][68] fp32
    float* wfr     = fsh + ROWS * FS;     // [5120] fragment-packed wefft
    float* w2fr    = wfr + 5120;          // [3200] fragment-packed W2
    float* c1sh    = w2fr + 3200;         // [80]
    float* b2sh    = c1sh + H1;           // [40]
    float* w3sh    = b2sh + H2;           // [40]
    float* scoresh = w3sh + H2;           // [208]
    float* red     = scoresh + ROWS;      // [256]
    float* attnsh  = red + NTHREADS;      // [208]
    float* outred  = attnsh + ROWS;       // [256]
    float* qsh     = outred + NTHREADS;   // [64]

    const int b    = blockIdx.x;
    const int tid  = threadIdx.x;
    const int w    = tid >> 5;
    const int lane = tid & 31;
    const int g    = lane >> 2;
    const int tg   = lane & 3;

    // ---------------- async facts staging: issue FIRST, consume later ----------
    {
        const float4* fb = (const float4*)(facts + (size_t)b * T_LEN * E_DIM);
        uint32_t fsh_base;
        asm("{ .reg .u64 t; cvta.to.shared.u64 t, %1; cvt.u32.u64 %0, t; }"
            : "=r"(fsh_base) : "l"(fsh));
        for (int i = tid; i < T_LEN * 16; i += NTHREADS) {
            int t = i >> 4, e4 = i & 15;
            cp_async16(fsh_base + (t * FS + e4 * 4) * 4, fb + i);
        }
        asm volatile("cp.async.commit_group;");
    }
    // prefetch this thread's mask bit early
    int mbit = 1;
    if (tid < T_LEN) mbit = mask[(size_t)b * T_LEN + tid];

    // zero pad rows [200,208) (cols 0..63 used by mma stripe 12)
    for (int i = tid; i < (ROWS - T_LEN) * 16; i += NTHREADS) {
        int t = T_LEN + (i >> 4), e4 = i & 15;
        *(float4*)&fsh[t * FS + e4 * 4] = make_float4(0.f, 0.f, 0.f, 0.f);
    }

    if (tid < E_DIM) qsh[tid] = query[(size_t)b * E_DIM + tid];
    if (tid < H2)    { b2sh[tid] = b2[tid]; w3sh[tid] = W3[tid]; }
    __syncthreads();    // qsh ready

    // ---------------- per-batch effective layer-1 weights (fragment-packed) ----
    // wefft[n][k] = W1[(64+k)*80+n] - W1[(128+k)*80+n] + q[k]*W1[(192+k)*80+n]
    // fragment order: fp = kt*320 + j*32 + (g*4+tg) -> pair (k=kt*8+tg, k+4) at n=j*8+g
    for (int fp = tid; fp < 2560; fp += NTHREADS) {
        int kt = fp / 320, rem = fp - kt * 320;
        int j = rem >> 5, l5 = rem & 31;
        int gg = l5 >> 2, tt = l5 & 3;
        int n = j * 8 + gg;
        int ka = kt * 8 + tt, kb = ka + 4;
        float va = W1[(64 + ka) * H1 + n] - W1[(128 + ka) * H1 + n] + qsh[ka] * W1[(192 + ka) * H1 + n];
        float vb = W1[(64 + kb) * H1 + n] - W1[(128 + kb) * H1 + n] + qsh[kb] * W1[(192 + kb) * H1 + n];
        *(float2*)&wfr[2 * fp] = make_float2(va, vb);
    }
    // W2 fragments: fp = kt*160 + j*32 + lane -> pair W2[(kt*8+tg)*40+n], W2[(kt*8+tg+4)*40+n]
    for (int fp = tid; fp < 1600; fp += NTHREADS) {
        int kt = fp / 160, rem = fp - kt * 160;
        int j = rem >> 5, l5 = rem & 31;
        int gg = l5 >> 2, tt = l5 & 3;
        int n = j * 8 + gg;
        int ka = kt * 8 + tt;
        *(float2*)&w2fr[2 * fp] = make_float2(W2[ka * H2 + n], W2[(ka + 4) * H2 + n]);
    }
    // c1 = b1 + q@(A+C)
    if (tid < H1) {
        float acc = b1[tid];
        #pragma unroll 8
        for (int e = 0; e < E_DIM; e++)
            acc += qsh[e] * (W1[e * H1 + tid] + W1[(128 + e) * H1 + tid]);
        c1sh[tid] = acc;
    }

    asm volatile("cp.async.wait_group 0;");
    __syncthreads();

    const uint32_t* fu = (const uint32_t*)fsh;

    // ---------------- per-stripe MLP (warp w handles stripes w, w+8) ------------
    for (int s = w; s < NSTRIPES; s += 8) {
        const int r0 = s * 16;

        // GEMM1: acc = F @ Weff^T
        float acc[10][4];
        #pragma unroll
        for (int j = 0; j < 10; j++)
            #pragma unroll
            for (int q = 0; q < 4; q++) acc[j][q] = 0.0f;

        #pragma unroll
        for (int kt = 0; kt < 8; kt++) {
            const int k0 = kt * 8 + tg;
            uint32_t a[4];
            a[0] = fu[(r0 + g    ) * FS + k0    ];
            a[1] = fu[(r0 + g + 8) * FS + k0    ];
            a[2] = fu[(r0 + g    ) * FS + k0 + 4];
            a[3] = fu[(r0 + g + 8) * FS + k0 + 4];
            const float2* wp = (const float2*)wfr + kt * 320 + lane;
            #pragma unroll
            for (int j = 0; j < 10; j++) {
                float2 bw = wp[j * 32];
                uint32_t bf[2] = { __float_as_uint(bw.x), __float_as_uint(bw.y) };
                mma_tf32(acc[j], a, bf);
            }
        }

        // fused sigmoid + shfl-exchange + GEMM2
        float acc2[5][4];
        #pragma unroll
        for (int j = 0; j < 5; j++)
            #pragma unroll
            for (int q = 0; q < 4; q++) acc2[j][q] = 0.0f;

        const int src_lo = (g << 2) + (tg >> 1);
        const int src_hi = src_lo + 2;
        const bool odd = (tg & 1);

        #pragma unroll
        for (int kt = 0; kt < 10; kt++) {
            const int n0 = kt * 8 + 2 * tg;
            float c1a = c1sh[n0], c1b = c1sh[n0 + 1];
            float s0 = sigm(acc[kt][0] + c1a);
            float s1 = sigm(acc[kt][1] + c1b);
            float s2 = sigm(acc[kt][2] + c1a);
            float s3 = sigm(acc[kt][3] + c1b);

            float v0 = __shfl_sync(0xFFFFFFFF, s0, src_lo);
            float v1 = __shfl_sync(0xFFFFFFFF, s1, src_lo);
            float a0 = odd ? v1 : v0;
            v0 = __shfl_sync(0xFFFFFFFF, s2, src_lo);
            v1 = __shfl_sync(0xFFFFFFFF, s3, src_lo);
            float a1 = odd ? v1 : v0;
            v0 = __shfl_sync(0xFFFFFFFF, s0, src_hi);
            v1 = __shfl_sync(0xFFFFFFFF, s1, src_hi);
            float a2 = odd ? v1 : v0;
            v0 = __shfl_sync(0xFFFFFFFF, s2, src_hi);
            v1 = __shfl_sync(0xFFFFFFFF, s3, src_hi);
            float a3 = odd ? v1 : v0;

            uint32_t a[4] = { __float_as_uint(a0), __float_as_uint(a1),
                              __float_as_uint(a2), __float_as_uint(a3) };
            const float2* wp = (const float2*)w2fr + kt * 160 + lane;
            #pragma unroll
            for (int j = 0; j < 5; j++) {
                float2 bw = wp[j * 32];
                uint32_t bf[2] = { __float_as_uint(bw.x), __float_as_uint(bw.y) };
                mma_tf32(acc2[j], a, bf);
            }
        }

        // epilogue: sigmoid, dot W3, quad-reduce, scores -> smem
        float s_lo = 0.0f, s_hi = 0.0f;
        #pragma unroll
        for (int j = 0; j < 5; j++) {
            const int n0 = j * 8 + 2 * tg;
            float bb0 = b2sh[n0], bb1 = b2sh[n0 + 1];
            float w30 = w3sh[n0], w31 = w3sh[n0 + 1];
            s_lo += sigm(acc2[j][0] + bb0) * w30 + sigm(acc2[j][1] + bb1) * w31;
            s_hi += sigm(acc2[j][2] + bb0) * w30 + sigm(acc2[j][3] + bb1) * w31;
        }
        s_lo += __shfl_xor_sync(0xFFFFFFFF, s_lo, 1);
        s_lo += __shfl_xor_sync(0xFFFFFFFF, s_lo, 2);
        s_hi += __shfl_xor_sync(0xFFFFFFFF, s_hi, 1);
        s_hi += __shfl_xor_sync(0xFFFFFFFF, s_hi, 2);

        if (tg == 0) {   // b3 omitted: constant shift cancels in softmax
            scoresh[r0 + g]     = s_lo;
            scoresh[r0 + g + 8] = s_hi;
        }
    }
    __syncthreads();

    // ---------------- masked softmax over T ----------------
    const float PADV = -4294967295.0f;   // -2^32 + 1
    float v;
    if (tid < T_LEN)
        v = (mbit == 1) ? scoresh[tid] : PADV;
    else
        v = -INFINITY;
    red[tid] = v;
    __syncthreads();
    #pragma unroll
    for (int off = 128; off > 0; off >>= 1) {
        if (tid < off) red[tid] = fmaxf(red[tid], red[tid + off]);
        __syncthreads();
    }
    float mmax = red[0];
    __syncthreads();
    float p = (tid < T_LEN) ? __expf(v - mmax) : 0.0f;
    red[tid] = p;
    __syncthreads();
    #pragma unroll
    for (int off = 128; off > 0; off >>= 1) {
        if (tid < off) red[tid] += red[tid + off];
        __syncthreads();
    }
    float inv = 1.0f / red[0];
    if (tid < ROWS) attnsh[tid] = p * inv;    // rows >= T_LEN get 0
    __syncthreads();

    // ---------------- out[b] = attn @ facts (smem-resident) ----------------
    {
        const int e = tid & 63;
        const int c = tid >> 6;                // 4 chunks of 52 rows
        float acc = 0.0f;
        const int t0 = c * 52;
        #pragma unroll 4
        for (int t = t0; t < t0 + 52; t++)
            acc = fmaf(attnsh[t], fsh[t * FS + e], acc);
        outred[c * 64 + e] = acc;
    }
    __syncthreads();
    if (tid < E_DIM)
        out[(size_t)b * E_DIM + tid] =
            outred[tid] + outred[64 + tid] + outred[128 + tid] + outred[192 + tid];
}

// ============================================================================
// launch
// ============================================================================
static inline size_t fused_smem_bytes() {
    size_t f = (size_t)ROWS * FS + 5120 + 3200 + H1 + H2 + H2 +
               ROWS + NTHREADS + ROWS + NTHREADS + E_DIM;
    return f * sizeof(float);
}

extern "C" void kernel_launch(void* const* d_in, const int* in_sizes, int n_in,
                              void* d_out, int out_size)
{
    const float* query = (const float*)d_in[0];
    const float* facts = (const float*)d_in[1];
    const int*   mask  = (const int*)  d_in[2];
    const float* W1    = (const float*)d_in[3];
    const float* b1    = (const float*)d_in[4];
    const float* W2    = (const float*)d_in[5];
    const float* b2    = (const float*)d_in[6];
    const float* W3    = (const float*)d_in[7];
    float* out = (float*)d_out;

    const int B = in_sizes[0] / E_DIM;

    static bool configured = false;
    if (!configured) {
        cudaFuncSetAttribute(fused_kernel,
                             cudaFuncAttributeMaxDynamicSharedMemorySize,
                             (int)fused_smem_bytes());
        configured = true;
    }

    fused_kernel<<<B, NTHREADS, fused_smem_bytes()>>>(query, facts, mask,
                                                      W1, b1, W2, b2, W3, out);
}